// round 13
// baseline (speedup 1.0000x reference)
#include <cuda_runtime.h>
#include <cstdint>

#define GRID_DIM   128
#define U_PIX      8192
#define N_TRK      3000
#define M_NEIGH    16
#define T_SIG      400
#define ADC_SAMPLE 50
#define NBINS      200          // T_TOTAL / ADC_SAMPLE
#define MAX_BINS   9            // ceil((400+49)/50)
#define GAIN       0.25f
#define PEDESTAL   74.0f
#define ADC_MAX    255.0f

// Scratch (allocation-free rule: __device__ globals)
// g_lut is NEVER invalidated: k_accum verifies each hit against unique_pix.
__device__ int   g_lut[GRID_DIM * GRID_DIM];     // (y,x) -> candidate pixel id
__device__ float g_acc[U_PIX * NBINS];           // per-pixel per-bin sums

// ---------------------------------------------------------------------------
// Kernel 1: LUT scatter only (zeroing of g_acc is a memset node in the graph)
// ---------------------------------------------------------------------------
__global__ void k_prep(const int2* __restrict__ unique_pix) {
    int tid = blockIdx.x * blockDim.x + threadIdx.x;
    if (tid < U_PIX) {
        int2 c = unique_pix[tid];
        g_lut[c.x * GRID_DIM + c.y] = tid;
    }
}

// ---------------------------------------------------------------------------
// Kernel 2: one warp per (track, neighbor) pair.  [R9 body — FROZEN except
// __ldcs streaming hint on the read-once signal loads.]
// 18 segment loads up front (MLP 18), one 5-stage butterfly over the
// 9-register bin vector (full ILP), lanes 0..8 flush with one REDG each.
// ---------------------------------------------------------------------------
__global__ void k_accum(const int2*  __restrict__ neigh,
                        const int2*  __restrict__ upix,
                        const float* __restrict__ sig,
                        const int*   __restrict__ starts) {
    int gwarp = (blockIdx.x * blockDim.x + threadIdx.x) >> 5;
    int lane  = threadIdx.x & 31;
    if (gwarp >= N_TRK * M_NEIGH) return;

    int2 c = neigh[gwarp];
    if (c.x < 0) return;                          // dead channel -> discard

    int  pid = g_lut[c.x * GRID_DIM + c.y];       // candidate (may be stale)
    int2 u   = upix[pid];
    if (u.x != c.x || u.y != c.y) return;         // verify: reject stale/no-match

    int start = starts[gwarp >> 4];               // M_NEIGH = 16
    int b0    = start / ADC_SAMPLE;               // 0..191
    int rel0  = start - b0 * ADC_SAMPLE;          // 0..49

    const float* s = sig + (size_t)gwarp * T_SIG;

    float v[MAX_BINS];
    #pragma unroll
    for (int i = 0; i < MAX_BINS; ++i) {
        int lo = i * ADC_SAMPLE - rel0;           if (lo < 0)     lo = 0;
        int hi = (i + 1) * ADC_SAMPLE - rel0;     if (hi > T_SIG) hi = T_SIG;
        int t  = lo + lane;
        float a = (t      < hi) ? __ldcs(s + t)      : 0.0f;   // streaming:
        float b = (t + 32 < hi) ? __ldcs(s + t + 32) : 0.0f;   // read-once data
        v[i] = a + b;
    }

    #pragma unroll
    for (int o = 16; o > 0; o >>= 1) {
        #pragma unroll
        for (int i = 0; i < MAX_BINS; ++i)
            v[i] += __shfl_xor_sync(0xffffffffu, v[i], o);
    }

    float mine = 0.0f;
    #pragma unroll
    for (int i = 0; i < MAX_BINS; ++i)
        if (lane == i) mine = v[i];

    if (lane < MAX_BINS)                          // b0+8 <= 199 always
        atomicAdd(&g_acc[(size_t)pid * NBINS + b0 + lane], mine);
}

// ---------------------------------------------------------------------------
// Kernel 3: TWO rows per warp.  [R6/R9 body — measured optimum: beats both
// the 1-row (R2) and 4-row (R11) variants.]
// ---------------------------------------------------------------------------
__global__ void k_final(float* __restrict__ out) {
    int gwarp = (blockIdx.x * blockDim.x + threadIdx.x) >> 5;  // 0..4095
    int lane  = threadIdx.x & 31;
    if (gwarp >= U_PIX / 2) return;

    int rowA = gwarp * 2, rowB = rowA + 1;
    const float4* a4 = reinterpret_cast<const float4*>(g_acc + (size_t)rowA * NBINS);
    const float4* b4 = reinterpret_cast<const float4*>(g_acc + (size_t)rowB * NBINS);
    float4* oa4 = reinterpret_cast<float4*>(out + (size_t)rowA * NBINS);
    float4* ob4 = reinterpret_cast<float4*>(out + (size_t)rowB * NBINS);

    const float4 z4 = make_float4(0.f, 0.f, 0.f, 0.f);
    bool act1 = (lane < NBINS / 4 - 32);          // lanes 0..17

    float4 xa0 = a4[lane];
    float4 xb0 = b4[lane];
    float4 xa1 = act1 ? a4[32 + lane] : z4;
    float4 xb1 = act1 ? b4[32 + lane] : z4;

    xa0.y += xa0.x;  xa0.z += xa0.y;  xa0.w += xa0.z;
    xa1.y += xa1.x;  xa1.z += xa1.y;  xa1.w += xa1.z;
    xb0.y += xb0.x;  xb0.z += xb0.y;  xb0.w += xb0.z;
    xb1.y += xb1.x;  xb1.z += xb1.y;  xb1.w += xb1.z;
    float sa0 = xa0.w, sa1 = xa1.w, sb0 = xb0.w, sb1 = xb1.w;

    float ia0 = sa0, ia1 = sa1, ib0 = sb0, ib1 = sb1;
    #pragma unroll
    for (int o = 1; o < 32; o <<= 1) {
        float ua0 = __shfl_up_sync(0xffffffffu, ia0, o);
        float ua1 = __shfl_up_sync(0xffffffffu, ia1, o);
        float ub0 = __shfl_up_sync(0xffffffffu, ib0, o);
        float ub1 = __shfl_up_sync(0xffffffffu, ib1, o);
        if (lane >= o) { ia0 += ua0; ia1 += ua1; ib0 += ub0; ib1 += ub1; }
    }
    float totA0 = __shfl_sync(0xffffffffu, ia0, 31);
    float totB0 = __shfl_sync(0xffffffffu, ib0, 31);
    float baseA0 = ia0 - sa0;
    float baseA1 = totA0 + (ia1 - sa1);
    float baseB0 = ib0 - sb0;
    float baseB1 = totB0 + (ib1 - sb1);

    float4 r;
    #define ADCV(x, b) fminf(fmaxf(((x) + (b)) * GAIN + PEDESTAL, 0.0f), ADC_MAX)
    r.x = ADCV(xa0.x, baseA0); r.y = ADCV(xa0.y, baseA0);
    r.z = ADCV(xa0.z, baseA0); r.w = ADCV(xa0.w, baseA0);
    oa4[lane] = r;
    r.x = ADCV(xb0.x, baseB0); r.y = ADCV(xb0.y, baseB0);
    r.z = ADCV(xb0.z, baseB0); r.w = ADCV(xb0.w, baseB0);
    ob4[lane] = r;
    if (act1) {
        r.x = ADCV(xa1.x, baseA1); r.y = ADCV(xa1.y, baseA1);
        r.z = ADCV(xa1.z, baseA1); r.w = ADCV(xa1.w, baseA1);
        oa4[32 + lane] = r;
        r.x = ADCV(xb1.x, baseB1); r.y = ADCV(xb1.y, baseB1);
        r.z = ADCV(xb1.z, baseB1); r.w = ADCV(xb1.w, baseB1);
        ob4[32 + lane] = r;
    }
    #undef ADCV
}

// ---------------------------------------------------------------------------
// Launch: memset node + 3 kernels   [R9 launch config exactly]
// ---------------------------------------------------------------------------
extern "C" void kernel_launch(void* const* d_in, const int* in_sizes, int n_in,
                              void* d_out, int out_size) {
    const int2*  neigh  = (const int2*) d_in[0];   // (3000, 16, 2) int32
    const int2*  upix   = (const int2*) d_in[1];   // (8192, 2) int32
    const float* sig    = (const float*)d_in[2];   // (3000, 16, 400) float32
    const int*   starts = (const int*)  d_in[3];   // (3000,) int32
    float*       out    = (float*)      d_out;     // (8192, 200) float32

    (void)in_sizes; (void)n_in; (void)out_size;

    void* acc_ptr = nullptr;
    cudaGetSymbolAddress(&acc_ptr, g_acc);
    cudaMemsetAsync(acc_ptr, 0, (size_t)U_PIX * NBINS * sizeof(float), 0);

    k_prep<<<(U_PIX + 255) / 256, 256>>>(upix);

    {
        int total_warps = N_TRK * M_NEIGH;         // 48000
        int threads = 256;                         // 8 warps/block -> 6000 blocks
        int blocks  = (total_warps * 32 + threads - 1) / threads;
        k_accum<<<blocks, threads>>>(neigh, upix, sig, starts);
    }
    {
        int warps   = U_PIX / 2;                   // 4096
        int threads = 256;
        int blocks  = (warps * 32 + threads - 1) / threads;   // 512
        k_final<<<blocks, threads>>>(out);
    }
}

// round 14
// speedup vs baseline: 1.0251x; 1.0251x over previous
#include <cuda_runtime.h>
#include <cstdint>

#define GRID_DIM   128
#define U_PIX      8192
#define N_TRK      3000
#define M_NEIGH    16
#define T_SIG      400
#define ADC_SAMPLE 50
#define NBINS      200          // T_TOTAL / ADC_SAMPLE
#define MAX_BINS   9            // ceil((400+49)/50)
#define GAIN       0.25f
#define PEDESTAL   74.0f
#define ADC_MAX    255.0f

// Scratch (allocation-free rule: __device__ globals)
// g_lut is NEVER invalidated: k_accum verifies each hit against unique_pix.
__device__ int   g_lut[GRID_DIM * GRID_DIM];     // (y,x) -> candidate pixel id
__device__ float g_acc[U_PIX * NBINS];           // per-pixel per-bin sums

// ---------------------------------------------------------------------------
// Kernel 1: LUT scatter only (zeroing of g_acc is a memset node in the graph)
// ---------------------------------------------------------------------------
__global__ void k_prep(const int2* __restrict__ unique_pix) {
    int tid = blockIdx.x * blockDim.x + threadIdx.x;
    if (tid < U_PIX) {
        int2 c = unique_pix[tid];
        g_lut[c.x * GRID_DIM + c.y] = tid;
    }
}

// ---------------------------------------------------------------------------
// Kernel 2: one warp per (track, neighbor) pair.  [R9 body — FROZEN.
// All seven restructurings (R3/R4/R5/R8/R10/R12/R13) measured slower.]
// 18 segment loads up front (MLP 18), one 5-stage butterfly over the
// 9-register bin vector (full ILP), lanes 0..8 flush with one REDG each.
// ---------------------------------------------------------------------------
__global__ void k_accum(const int2*  __restrict__ neigh,
                        const int2*  __restrict__ upix,
                        const float* __restrict__ sig,
                        const int*   __restrict__ starts) {
    int gwarp = (blockIdx.x * blockDim.x + threadIdx.x) >> 5;
    int lane  = threadIdx.x & 31;
    if (gwarp >= N_TRK * M_NEIGH) return;

    int2 c = neigh[gwarp];
    if (c.x < 0) return;                          // dead channel -> discard

    int  pid = g_lut[c.x * GRID_DIM + c.y];       // candidate (may be stale)
    int2 u   = upix[pid];
    if (u.x != c.x || u.y != c.y) return;         // verify: reject stale/no-match

    int start = starts[gwarp >> 4];               // M_NEIGH = 16
    int b0    = start / ADC_SAMPLE;               // 0..191
    int rel0  = start - b0 * ADC_SAMPLE;          // 0..49

    const float* s = sig + (size_t)gwarp * T_SIG;

    float v[MAX_BINS];
    #pragma unroll
    for (int i = 0; i < MAX_BINS; ++i) {
        int lo = i * ADC_SAMPLE - rel0;           if (lo < 0)     lo = 0;
        int hi = (i + 1) * ADC_SAMPLE - rel0;     if (hi > T_SIG) hi = T_SIG;
        int t  = lo + lane;
        float a = (t      < hi) ? s[t]      : 0.0f;
        float b = (t + 32 < hi) ? s[t + 32] : 0.0f;  // segment length <= 50
        v[i] = a + b;
    }

    #pragma unroll
    for (int o = 16; o > 0; o >>= 1) {
        #pragma unroll
        for (int i = 0; i < MAX_BINS; ++i)
            v[i] += __shfl_xor_sync(0xffffffffu, v[i], o);
    }

    float mine = 0.0f;
    #pragma unroll
    for (int i = 0; i < MAX_BINS; ++i)
        if (lane == i) mine = v[i];

    if (lane < MAX_BINS)                          // b0+8 <= 199 always
        atomicAdd(&g_acc[(size_t)pid * NBINS + b0 + lane], mine);
}

// ---------------------------------------------------------------------------
// Kernel 3: TWO rows per warp.  [R6/R9 body — measured optimum: beats both
// the 1-row (R2) and 4-row (R11) variants.]
// ---------------------------------------------------------------------------
__global__ void k_final(float* __restrict__ out) {
    int gwarp = (blockIdx.x * blockDim.x + threadIdx.x) >> 5;  // 0..4095
    int lane  = threadIdx.x & 31;
    if (gwarp >= U_PIX / 2) return;

    int rowA = gwarp * 2, rowB = rowA + 1;
    const float4* a4 = reinterpret_cast<const float4*>(g_acc + (size_t)rowA * NBINS);
    const float4* b4 = reinterpret_cast<const float4*>(g_acc + (size_t)rowB * NBINS);
    float4* oa4 = reinterpret_cast<float4*>(out + (size_t)rowA * NBINS);
    float4* ob4 = reinterpret_cast<float4*>(out + (size_t)rowB * NBINS);

    const float4 z4 = make_float4(0.f, 0.f, 0.f, 0.f);
    bool act1 = (lane < NBINS / 4 - 32);          // lanes 0..17

    float4 xa0 = a4[lane];
    float4 xb0 = b4[lane];
    float4 xa1 = act1 ? a4[32 + lane] : z4;
    float4 xb1 = act1 ? b4[32 + lane] : z4;

    xa0.y += xa0.x;  xa0.z += xa0.y;  xa0.w += xa0.z;
    xa1.y += xa1.x;  xa1.z += xa1.y;  xa1.w += xa1.z;
    xb0.y += xb0.x;  xb0.z += xb0.y;  xb0.w += xb0.z;
    xb1.y += xb1.x;  xb1.z += xb1.y;  xb1.w += xb1.z;
    float sa0 = xa0.w, sa1 = xa1.w, sb0 = xb0.w, sb1 = xb1.w;

    float ia0 = sa0, ia1 = sa1, ib0 = sb0, ib1 = sb1;
    #pragma unroll
    for (int o = 1; o < 32; o <<= 1) {
        float ua0 = __shfl_up_sync(0xffffffffu, ia0, o);
        float ua1 = __shfl_up_sync(0xffffffffu, ia1, o);
        float ub0 = __shfl_up_sync(0xffffffffu, ib0, o);
        float ub1 = __shfl_up_sync(0xffffffffu, ib1, o);
        if (lane >= o) { ia0 += ua0; ia1 += ua1; ib0 += ub0; ib1 += ub1; }
    }
    float totA0 = __shfl_sync(0xffffffffu, ia0, 31);
    float totB0 = __shfl_sync(0xffffffffu, ib0, 31);
    float baseA0 = ia0 - sa0;
    float baseA1 = totA0 + (ia1 - sa1);
    float baseB0 = ib0 - sb0;
    float baseB1 = totB0 + (ib1 - sb1);

    float4 r;
    #define ADCV(x, b) fminf(fmaxf(((x) + (b)) * GAIN + PEDESTAL, 0.0f), ADC_MAX)
    r.x = ADCV(xa0.x, baseA0); r.y = ADCV(xa0.y, baseA0);
    r.z = ADCV(xa0.z, baseA0); r.w = ADCV(xa0.w, baseA0);
    oa4[lane] = r;
    r.x = ADCV(xb0.x, baseB0); r.y = ADCV(xb0.y, baseB0);
    r.z = ADCV(xb0.z, baseB0); r.w = ADCV(xb0.w, baseB0);
    ob4[lane] = r;
    if (act1) {
        r.x = ADCV(xa1.x, baseA1); r.y = ADCV(xa1.y, baseA1);
        r.z = ADCV(xa1.z, baseA1); r.w = ADCV(xa1.w, baseA1);
        oa4[32 + lane] = r;
        r.x = ADCV(xb1.x, baseB1); r.y = ADCV(xb1.y, baseB1);
        r.z = ADCV(xb1.z, baseB1); r.w = ADCV(xb1.w, baseB1);
        ob4[32 + lane] = r;
    }
    #undef ADCV
}

// ---------------------------------------------------------------------------
// Launch: memset node + 3 kernels   [R9 exactly]
// ---------------------------------------------------------------------------
extern "C" void kernel_launch(void* const* d_in, const int* in_sizes, int n_in,
                              void* d_out, int out_size) {
    const int2*  neigh  = (const int2*) d_in[0];   // (3000, 16, 2) int32
    const int2*  upix   = (const int2*) d_in[1];   // (8192, 2) int32
    const float* sig    = (const float*)d_in[2];   // (3000, 16, 400) float32
    const int*   starts = (const int*)  d_in[3];   // (3000,) int32
    float*       out    = (float*)      d_out;     // (8192, 200) float32

    (void)in_sizes; (void)n_in; (void)out_size;

    void* acc_ptr = nullptr;
    cudaGetSymbolAddress(&acc_ptr, g_acc);
    cudaMemsetAsync(acc_ptr, 0, (size_t)U_PIX * NBINS * sizeof(float), 0);

    k_prep<<<(U_PIX + 255) / 256, 256>>>(upix);

    {
        int total_warps = N_TRK * M_NEIGH;         // 48000
        int threads = 256;                         // 8 warps/block -> 6000 blocks
        int blocks  = (total_warps * 32 + threads - 1) / threads;
        k_accum<<<blocks, threads>>>(neigh, upix, sig, starts);
    }
    {
        int warps   = U_PIX / 2;                   // 4096
        int threads = 256;
        int blocks  = (warps * 32 + threads - 1) / threads;   // 512
        k_final<<<blocks, threads>>>(out);
    }
}

// round 15
// speedup vs baseline: 1.0918x; 1.0651x over previous
#include <cuda_runtime.h>
#include <cstdint>

#define GRID_DIM   128
#define U_PIX      8192
#define N_TRK      3000
#define M_NEIGH    16
#define T_SIG      400
#define ADC_SAMPLE 50
#define NBINS      200          // T_TOTAL / ADC_SAMPLE
#define MAX_BINS   9            // ceil((400+49)/50)
#define GAIN       0.25f
#define PEDESTAL   74.0f
#define ADC_MAX    255.0f

// Scratch (allocation-free rule: __device__ globals)
// g_lut is NEVER invalidated: k_accum verifies each hit against unique_pix.
__device__ int   g_lut[GRID_DIM * GRID_DIM];     // (y,x) -> candidate pixel id
__device__ float g_acc[U_PIX * NBINS];           // per-pixel per-bin sums

// ---------------------------------------------------------------------------
// Kernel 1: zero accumulator (vectorized grid-stride) + LUT scatter — ONE
// node. (R6 measured this ~equal to memset-node + separate prep; merging
// removes one graph-node boundary.)
// ---------------------------------------------------------------------------
__global__ void k_prep(const int2* __restrict__ unique_pix) {
    int tid    = blockIdx.x * blockDim.x + threadIdx.x;
    int stride = gridDim.x * blockDim.x;
    float4* acc4 = reinterpret_cast<float4*>(g_acc);
    const int n4 = (U_PIX * NBINS) / 4;           // 409600
    const float4 z4 = make_float4(0.f, 0.f, 0.f, 0.f);
    for (int i = tid; i < n4; i += stride) acc4[i] = z4;
    if (tid < U_PIX) {
        int2 c = unique_pix[tid];
        g_lut[c.x * GRID_DIM + c.y] = tid;
    }
}

// ---------------------------------------------------------------------------
// Kernel 2: one warp per (track, neighbor) pair.  [R9 body — FROZEN.
// Seven restructurings (R3/R4/R5/R8/R10/R12/R13) all measured slower.]
// 18 segment loads up front (MLP 18), one 5-stage butterfly over the
// 9-register bin vector (full ILP), lanes 0..8 flush with one REDG each.
// ---------------------------------------------------------------------------
__global__ void k_accum(const int2*  __restrict__ neigh,
                        const int2*  __restrict__ upix,
                        const float* __restrict__ sig,
                        const int*   __restrict__ starts) {
    int gwarp = (blockIdx.x * blockDim.x + threadIdx.x) >> 5;
    int lane  = threadIdx.x & 31;
    if (gwarp >= N_TRK * M_NEIGH) return;

    int2 c = neigh[gwarp];
    if (c.x < 0) return;                          // dead channel -> discard

    int  pid = g_lut[c.x * GRID_DIM + c.y];       // candidate (may be stale)
    int2 u   = upix[pid];
    if (u.x != c.x || u.y != c.y) return;         // verify: reject stale/no-match

    int start = starts[gwarp >> 4];               // M_NEIGH = 16
    int b0    = start / ADC_SAMPLE;               // 0..191
    int rel0  = start - b0 * ADC_SAMPLE;          // 0..49

    const float* s = sig + (size_t)gwarp * T_SIG;

    float v[MAX_BINS];
    #pragma unroll
    for (int i = 0; i < MAX_BINS; ++i) {
        int lo = i * ADC_SAMPLE - rel0;           if (lo < 0)     lo = 0;
        int hi = (i + 1) * ADC_SAMPLE - rel0;     if (hi > T_SIG) hi = T_SIG;
        int t  = lo + lane;
        float a = (t      < hi) ? s[t]      : 0.0f;
        float b = (t + 32 < hi) ? s[t + 32] : 0.0f;  // segment length <= 50
        v[i] = a + b;
    }

    #pragma unroll
    for (int o = 16; o > 0; o >>= 1) {
        #pragma unroll
        for (int i = 0; i < MAX_BINS; ++i)
            v[i] += __shfl_xor_sync(0xffffffffu, v[i], o);
    }

    float mine = 0.0f;
    #pragma unroll
    for (int i = 0; i < MAX_BINS; ++i)
        if (lane == i) mine = v[i];

    if (lane < MAX_BINS)                          // b0+8 <= 199 always
        atomicAdd(&g_acc[(size_t)pid * NBINS + b0 + lane], mine);
}

// ---------------------------------------------------------------------------
// Kernel 3: TWO rows per warp.  [R6/R9 body — measured optimum: beats both
// the 1-row (R2) and 4-row (R11) variants.]
// ---------------------------------------------------------------------------
__global__ void k_final(float* __restrict__ out) {
    int gwarp = (blockIdx.x * blockDim.x + threadIdx.x) >> 5;  // 0..4095
    int lane  = threadIdx.x & 31;
    if (gwarp >= U_PIX / 2) return;

    int rowA = gwarp * 2, rowB = rowA + 1;
    const float4* a4 = reinterpret_cast<const float4*>(g_acc + (size_t)rowA * NBINS);
    const float4* b4 = reinterpret_cast<const float4*>(g_acc + (size_t)rowB * NBINS);
    float4* oa4 = reinterpret_cast<float4*>(out + (size_t)rowA * NBINS);
    float4* ob4 = reinterpret_cast<float4*>(out + (size_t)rowB * NBINS);

    const float4 z4 = make_float4(0.f, 0.f, 0.f, 0.f);
    bool act1 = (lane < NBINS / 4 - 32);          // lanes 0..17

    float4 xa0 = a4[lane];
    float4 xb0 = b4[lane];
    float4 xa1 = act1 ? a4[32 + lane] : z4;
    float4 xb1 = act1 ? b4[32 + lane] : z4;

    xa0.y += xa0.x;  xa0.z += xa0.y;  xa0.w += xa0.z;
    xa1.y += xa1.x;  xa1.z += xa1.y;  xa1.w += xa1.z;
    xb0.y += xb0.x;  xb0.z += xb0.y;  xb0.w += xb0.z;
    xb1.y += xb1.x;  xb1.z += xb1.y;  xb1.w += xb1.z;
    float sa0 = xa0.w, sa1 = xa1.w, sb0 = xb0.w, sb1 = xb1.w;

    float ia0 = sa0, ia1 = sa1, ib0 = sb0, ib1 = sb1;
    #pragma unroll
    for (int o = 1; o < 32; o <<= 1) {
        float ua0 = __shfl_up_sync(0xffffffffu, ia0, o);
        float ua1 = __shfl_up_sync(0xffffffffu, ia1, o);
        float ub0 = __shfl_up_sync(0xffffffffu, ib0, o);
        float ub1 = __shfl_up_sync(0xffffffffu, ib1, o);
        if (lane >= o) { ia0 += ua0; ia1 += ua1; ib0 += ub0; ib1 += ub1; }
    }
    float totA0 = __shfl_sync(0xffffffffu, ia0, 31);
    float totB0 = __shfl_sync(0xffffffffu, ib0, 31);
    float baseA0 = ia0 - sa0;
    float baseA1 = totA0 + (ia1 - sa1);
    float baseB0 = ib0 - sb0;
    float baseB1 = totB0 + (ib1 - sb1);

    float4 r;
    #define ADCV(x, b) fminf(fmaxf(((x) + (b)) * GAIN + PEDESTAL, 0.0f), ADC_MAX)
    r.x = ADCV(xa0.x, baseA0); r.y = ADCV(xa0.y, baseA0);
    r.z = ADCV(xa0.z, baseA0); r.w = ADCV(xa0.w, baseA0);
    oa4[lane] = r;
    r.x = ADCV(xb0.x, baseB0); r.y = ADCV(xb0.y, baseB0);
    r.z = ADCV(xb0.z, baseB0); r.w = ADCV(xb0.w, baseB0);
    ob4[lane] = r;
    if (act1) {
        r.x = ADCV(xa1.x, baseA1); r.y = ADCV(xa1.y, baseA1);
        r.z = ADCV(xa1.z, baseA1); r.w = ADCV(xa1.w, baseA1);
        oa4[32 + lane] = r;
        r.x = ADCV(xb1.x, baseB1); r.y = ADCV(xb1.y, baseB1);
        r.z = ADCV(xb1.z, baseB1); r.w = ADCV(xb1.w, baseB1);
        ob4[32 + lane] = r;
    }
    #undef ADCV
}

// ---------------------------------------------------------------------------
// Launch: 3 nodes (merged prep + accum + final)
// ---------------------------------------------------------------------------
extern "C" void kernel_launch(void* const* d_in, const int* in_sizes, int n_in,
                              void* d_out, int out_size) {
    const int2*  neigh  = (const int2*) d_in[0];   // (3000, 16, 2) int32
    const int2*  upix   = (const int2*) d_in[1];   // (8192, 2) int32
    const float* sig    = (const float*)d_in[2];   // (3000, 16, 400) float32
    const int*   starts = (const int*)  d_in[3];   // (3000,) int32
    float*       out    = (float*)      d_out;     // (8192, 200) float32

    (void)in_sizes; (void)n_in; (void)out_size;

    k_prep<<<1024, 256>>>(upix);

    {
        int total_warps = N_TRK * M_NEIGH;         // 48000
        int threads = 256;                         // 8 warps/block -> 6000 blocks
        int blocks  = (total_warps * 32 + threads - 1) / threads;
        k_accum<<<blocks, threads>>>(neigh, upix, sig, starts);
    }
    {
        int warps   = U_PIX / 2;                   // 4096
        int threads = 256;
        int blocks  = (warps * 32 + threads - 1) / threads;   // 512
        k_final<<<blocks, threads>>>(out);
    }
}